// round 3
// baseline (speedup 1.0000x reference)
#include <cuda_runtime.h>

#define NTHREADS 512
#define NWARPS   16
#define RB       8      // rows per warp batch

typedef unsigned long long u64;

// ---- packed f32x2 helpers (FFMA2 path, PTX-only per SASS_QUICKREF) ----
__device__ __forceinline__ u64 fma2(u64 a, u64 b, u64 c) {
    u64 d;
    asm("fma.rn.f32x2 %0, %1, %2, %3;" : "=l"(d) : "l"(a), "l"(b), "l"(c));
    return d;
}
__device__ __forceinline__ float hsum2(u64 a) {
    float lo, hi;
    asm("mov.b64 {%0,%1}, %2;" : "=f"(lo), "=f"(hi) : "l"(a));
    return lo + hi;
}

// ---- shared memory layout (float offsets) ----
#define OFF_W1  0
#define SZ_W1   (64 * 132)          // stride 132: conflict-free per-lane LDS.128
#define OFF_W2  (OFF_W1 + SZ_W1)
#define SZ_W2   (32 * 132)
#define OFF_WF  (OFF_W2 + SZ_W2)
#define SZ_WF   (128 * 68)          // stride 68
#define OFF_B1  (OFF_WF + SZ_WF)
#define OFF_B2  (OFF_B1 + 64)
#define OFF_BF  (OFF_B2 + 32)
#define OFF_X   (OFF_BF + 128)
#define SZ_X    (NWARPS * RB * 128)
#define OFF_O   (OFF_X + SZ_X)
#define SZ_O    (NWARPS * RB * 64)
#define SMEM_FLOATS (OFF_O + SZ_O)

// Final layer: out[r][dd] = bf[dd] + sum_{u<32*UC/8} o[r][u] * Wf[dd][u]
// Each lane handles dd = lane + 32k, k=0..3, all 8 rows at once (acc in regs).
template<int UC>
__device__ __forceinline__ void final_layer(const float* __restrict__ sOw,
                                            const float* __restrict__ sWf,
                                            const float bfr[4],
                                            float* __restrict__ out,
                                            long r0, int lane)
{
    u64 acc[RB][4];
    #pragma unroll
    for (int r = 0; r < RB; r++) {
        #pragma unroll
        for (int k = 0; k < 4; k++) acc[r][k] = 0ull;
    }
    #pragma unroll
    for (int uc = 0; uc < UC; uc++) {
        ulonglong2 wf[4];
        #pragma unroll
        for (int k = 0; k < 4; k++)
            wf[k] = *reinterpret_cast<const ulonglong2*>(sWf + (lane + 32 * k) * 68 + uc * 4);
        #pragma unroll
        for (int r = 0; r < RB; r++) {
            ulonglong2 o2 = *reinterpret_cast<const ulonglong2*>(sOw + r * 64 + uc * 4);
            #pragma unroll
            for (int k = 0; k < 4; k++) {
                acc[r][k] = fma2(o2.x, wf[k].x, acc[r][k]);
                acc[r][k] = fma2(o2.y, wf[k].y, acc[r][k]);
            }
        }
    }
    #pragma unroll
    for (int r = 0; r < RB; r++) {
        float* orow = out + (r0 + r) * 128;
        #pragma unroll
        for (int k = 0; k < 4; k++)
            orow[lane + 32 * k] = hsum2(acc[r][k]) + bfr[k];
    }
}

__global__ void __launch_bounds__(NTHREADS, 1)
dynlayer_kernel(const float* __restrict__ X,  const float* __restrict__ W1,
                const float* __restrict__ b1, const float* __restrict__ W2,
                const float* __restrict__ b2, const float* __restrict__ Wf,
                const float* __restrict__ bf, float* __restrict__ out, int nrows)
{
    extern __shared__ float sm[];
    const int tid = threadIdx.x;

    // Stage weights once per CTA (padded strides for conflict-free reads)
    for (int i = tid; i < 64 * 128; i += NTHREADS) sm[OFF_W1 + (i >> 7) * 132 + (i & 127)] = W1[i];
    for (int i = tid; i < 32 * 128; i += NTHREADS) sm[OFF_W2 + (i >> 7) * 132 + (i & 127)] = W2[i];
    for (int i = tid; i < 128 * 64; i += NTHREADS) sm[OFF_WF + (i >> 6) * 68  + (i & 63)]  = Wf[i];
    if (tid < 64)  sm[OFF_B1 + tid] = b1[tid];
    if (tid < 32)  sm[OFF_B2 + tid] = b2[tid];
    if (tid < 128) sm[OFF_BF + tid] = bf[tid];
    __syncthreads();

    const int warp = tid >> 5, lane = tid & 31;
    float* sXw = sm + OFF_X + warp * (RB * 128);
    float* sOw = sm + OFF_O + warp * (RB * 64);
    const float* sW1 = sm + OFF_W1;
    const float* sW2 = sm + OFF_W2;
    const float* sWf = sm + OFF_WF;

    float bfr[4];
    #pragma unroll
    for (int k = 0; k < 4; k++) bfr[k] = sm[OFF_BF + lane + 32 * k];
    const float b2r  = sm[OFF_B2 + lane];
    const float b1r  = sm[OFF_B1 + lane];
    const float b1r2 = sm[OFF_B1 + lane + 32];

    const int nb = nrows / RB;
    const int stride = gridDim.x * NWARPS;

    for (int b = (int)blockIdx.x * NWARPS + warp; b < nb; b += stride) {
        const long r0 = (long)b * RB;

        // ---- load 8 rows of x (coalesced float4), per-row abs-sum reduction ----
        float4 g[RB];
        const float4* X4 = reinterpret_cast<const float4*>(X) + r0 * 32 + lane;
        #pragma unroll
        for (int r = 0; r < RB; r++) g[r] = X4[r * 32];
        float s[RB];
        #pragma unroll
        for (int r = 0; r < RB; r++)
            s[r] = fabsf(g[r].x) + fabsf(g[r].y) + fabsf(g[r].z) + fabsf(g[r].w);
        #pragma unroll
        for (int off = 16; off > 0; off >>= 1) {
            #pragma unroll
            for (int r = 0; r < RB; r++)
                s[r] += __shfl_xor_sync(0xffffffffu, s[r], off);
        }
        unsigned m = 0;
        #pragma unroll
        for (int r = 0; r < RB; r++) {
            reinterpret_cast<float4*>(sXw + r * 128)[lane] = g[r];
            if (s[r] > 128.0f) m |= (1u << r);   // sum > 128  <=>  mean > 1.0
        }
        __syncwarp();

        if (m == 0u) {
            // ---- fast path: all 8 rows take branch2 (32 units), lane = unit ----
            u64 aA[RB], aB[RB];
            #pragma unroll
            for (int r = 0; r < RB; r++) { aA[r] = 0ull; aB[r] = 0ull; }
            const float* w = sW2 + lane * 132;
            #pragma unroll 8
            for (int dc = 0; dc < 32; dc++) {
                ulonglong2 w2 = *reinterpret_cast<const ulonglong2*>(w + dc * 4);
                #pragma unroll
                for (int r = 0; r < RB; r++) {
                    ulonglong2 x2 = *reinterpret_cast<const ulonglong2*>(sXw + r * 128 + dc * 4);
                    aA[r] = fma2(x2.x, w2.x, aA[r]);
                    aB[r] = fma2(x2.y, w2.y, aB[r]);
                }
            }
            #pragma unroll
            for (int r = 0; r < RB; r++) {
                float o = hsum2(aA[r]) + hsum2(aB[r]) + b2r;
                sOw[r * 64 + lane] = fmaxf(o, 0.0f);
            }
            __syncwarp();
            final_layer<8>(sOw, sWf, bfr, out, r0, lane);
        } else {
            // ---- rare mixed path: per-row weight select, zero-pad o to 64 ----
            #pragma unroll 1
            for (int r = 0; r < RB; r++) {
                const bool mk = (m >> r) & 1u;
                const float* W  = mk ? sW1 : sW2;
                const float* xr = sXw + r * 128;
                const float* w0 = W + lane * 132;
                const float* w1 = sW1 + (lane + 32) * 132;
                u64 aA = 0ull, aB = 0ull, cA = 0ull, cB = 0ull;
                #pragma unroll 8
                for (int dc = 0; dc < 32; dc++) {
                    ulonglong2 x2 = *reinterpret_cast<const ulonglong2*>(xr + dc * 4);
                    ulonglong2 wv = *reinterpret_cast<const ulonglong2*>(w0 + dc * 4);
                    aA = fma2(x2.x, wv.x, aA);
                    aB = fma2(x2.y, wv.y, aB);
                    if (mk) {
                        ulonglong2 wb = *reinterpret_cast<const ulonglong2*>(w1 + dc * 4);
                        cA = fma2(x2.x, wb.x, cA);
                        cB = fma2(x2.y, wb.y, cB);
                    }
                }
                const float bb = mk ? b1r : b2r;
                sOw[r * 64 + lane] = fmaxf(hsum2(aA) + hsum2(aB) + bb, 0.0f);
                float ohi = 0.0f;
                if (mk) ohi = fmaxf(hsum2(cA) + hsum2(cB) + b1r2, 0.0f);
                sOw[r * 64 + lane + 32] = ohi;
            }
            __syncwarp();
            final_layer<16>(sOw, sWf, bfr, out, r0, lane);
        }
        __syncwarp();
    }
}

extern "C" void kernel_launch(void* const* d_in, const int* in_sizes, int n_in,
                              void* d_out, int out_size)
{
    const float* X  = (const float*)d_in[0];
    const float* W1 = (const float*)d_in[1];
    const float* b1 = (const float*)d_in[2];
    const float* W2 = (const float*)d_in[3];
    const float* b2 = (const float*)d_in[4];
    const float* Wf = (const float*)d_in[5];
    const float* bf = (const float*)d_in[6];
    float* out = (float*)d_out;

    const int nrows = in_sizes[0] / 128;
    const size_t smem = SMEM_FLOATS * sizeof(float);

    cudaFuncSetAttribute(dynlayer_kernel,
                         cudaFuncAttributeMaxDynamicSharedMemorySize, (int)smem);

    int nsm = 148;
    cudaDeviceGetAttribute(&nsm, cudaDevAttrMultiProcessorCount, 0);

    dynlayer_kernel<<<nsm, NTHREADS, smem>>>(X, W1, b1, W2, b2, Wf, bf, out, nrows);
}